// round 5
// baseline (speedup 1.0000x reference)
#include <cuda_runtime.h>

#define BT 32768
#define CT 4194304
static const long long BCT = 33554432LL;

struct Ptrs { const float *iw[4], *ib[4], *cb[4], *ow[4], *ob[4]; };

__constant__ int c_mod[8] = {0,1,1,2,2,3,3,3};
__constant__ int c_sim[8] = {0,0,1,0,1,0,1,2};
__constant__ unsigned c_dep[8] = {0,0,2,7,15,31,63,127};

__device__ __align__(16) float g_cbn[8][1024][8];
__device__ __align__(16) float g_M[8][8][8][8];   // [s][j][dj][d]
__device__ float g_bvec[8][8];
__device__ __align__(16) float g_Wt[1024*64];     // [c][r]
__device__ __align__(16) float g_WoT[64*1024];    // [r][c]
__device__ float g_obv[1024*4];
__device__ float g_mask[8];
__device__ double g_commit;
__device__ __align__(16) float g_A[64*BT];        // plane-major [r][col]
__device__ __align__(16) float g_code[64*BT];     // plane-major [r][col]

__global__ void k_init(const int* noise, const int* recon, const float* rr) {
    int i = threadIdx.x;
    if (i == 0) g_commit = 0.0;
    if (i < 8) g_mask[i] = noise[i] ? (recon[i] ? 1.f : 0.f) : rr[i];
}

__global__ void k_prepCB(Ptrs P) {
    int s = blockIdx.x, m = c_mod[s], si = c_sim[s];
    const float* src = P.cb[m] + (long long)si * 1024 * 8;
    for (int k = threadIdx.x; k < 1024; k += blockDim.x) {
        float v[8], ss = 0.f;
#pragma unroll
        for (int d = 0; d < 8; d++) { v[d] = src[k*8+d]; ss += v[d]*v[d]; }
        float n = fmaxf(__fsqrt_rn(ss), 1e-12f);
#pragma unroll
        for (int d = 0; d < 8; d++) g_cbn[s][k][d] = __fdiv_rn(v[d], n);
    }
}

__global__ void k_prepW(Ptrs P) {
    int idx = blockIdx.x * 1024 + threadIdx.x;   // 65536
    int c = idx >> 6, r = idx & 63, s = r >> 3, d = r & 7;
    int m = c_mod[s], si = c_sim[s];
    g_Wt[c*64 + r]   = P.iw[m][(si*8 + d)*1024 + c];
    g_WoT[r*1024 + c] = P.ow[m][((long long)si*1024 + c)*8 + d];
    if (blockIdx.x == 0) {
        int cc = threadIdx.x;
        g_obv[cc*4+0] = P.ob[0][cc];
        g_obv[cc*4+1] = P.ob[1][cc] + P.ob[1][1024+cc];
        g_obv[cc*4+2] = P.ob[2][cc] + P.ob[2][1024+cc];
        g_obv[cc*4+3] = P.ob[3][cc] + P.ob[3][1024+cc] + P.ob[3][2048+cc];
    }
}

__global__ void k_prepM(Ptrs P) {   // grid (8,8), 512 threads
    int s = blockIdx.x, j = blockIdx.y;
    if (!((c_dep[s] >> j) & 1)) return;
    int d = (threadIdx.x >> 3) & 7, dj = threadIdx.x >> 6, sub = threadIdx.x & 7;
    const float* iw = P.iw[c_mod[s]] + (c_sim[s]*8 + d)*1024;
    const float* ow = P.ow[c_mod[j]] + (long long)c_sim[j]*8192 + dj;
    float a = 0.f;
    for (int c = sub; c < 1024; c += 8) a += iw[c] * ow[c*8];
#pragma unroll
    for (int o = 4; o; o >>= 1) a += __shfl_down_sync(0xffffffffu, a, o, 8);
    if (sub == 0) g_M[s][j][dj][d] = a;
}

__global__ void k_prepB(Ptrs P) {   // grid 8, 256 threads
    int s = blockIdx.x, d = threadIdx.x >> 5, ln = threadIdx.x & 31;
    const float* iw = P.iw[c_mod[s]] + (c_sim[s]*8 + d)*1024;
    float a = 0.f;
    for (int j = 0; j < 8; j++) if ((c_dep[s] >> j) & 1) {
        const float* ob = P.ob[c_mod[j]] + c_sim[j]*1024;
        for (int c = ln; c < 1024; c += 32) a += iw[c] * ob[c];
    }
#pragma unroll
    for (int o = 16; o; o >>= 1) a += __shfl_down_sync(0xffffffffu, a, o);
    if (ln == 0) g_bvec[s][d] = P.ib[c_mod[s]][c_sim[s]*8 + d] - a;
}

// ---- A[r][col] = Wt^T @ x : 512 blocks (64 cols each) x 256 threads ----
__global__ void k_project(const float* __restrict__ x) {
    __shared__ __align__(16) float Ws[64][64], Xs[64][64];
    int col0 = blockIdx.x * 64;
    int b = col0 >> 12, t0 = col0 & 4095;
    const float* xb = x + (long long)b*CT + t0;
    int tid = threadIdx.x, tr = tid >> 4, tc = tid & 15;
    float acc[4][4] = {};
    for (int c0 = 0; c0 < 1024; c0 += 64) {
        __syncthreads();
        for (int i = tid; i < 1024; i += 256) {
            int k = i >> 4, q = i & 15;
            *(float4*)&Ws[k][q*4] = *(const float4*)&g_Wt[(c0+k)*64 + q*4];
            *(float4*)&Xs[k][q*4] = *(const float4*)&xb[(long long)(c0+k)*4096 + q*4];
        }
        __syncthreads();
#pragma unroll 8
        for (int k = 0; k < 64; k++) {
            float4 w = *(float4*)&Ws[k][tr*4];
            float4 v = *(float4*)&Xs[k][tc*4];
            float wv[4] = {w.x,w.y,w.z,w.w}, xv[4] = {v.x,v.y,v.z,v.w};
#pragma unroll
            for (int i = 0; i < 4; i++)
#pragma unroll
                for (int j = 0; j < 4; j++) acc[i][j] += wv[i]*xv[j];
        }
    }
#pragma unroll
    for (int i = 0; i < 4; i++) {
        float4 o = {acc[i][0], acc[i][1], acc[i][2], acc[i][3]};
        *(float4*)&g_A[(tr*4+i)*BT + col0 + tc*4] = o;
    }
}

// ---- quantize: 128 blocks x 256 threads (1 col/thread) ----
__global__ void k_quant(Ptrs P) {
    __shared__ __align__(16) float cbs[1024][8];
    __shared__ float Ms[8][8][8];
    __shared__ float bv[8];
    int col = blockIdx.x * 256 + threadIdx.x;
    float code[8][8];
    float cacc = 0.f;
#pragma unroll
    for (int s = 0; s < 8; s++) {
        __syncthreads();
        for (int i = threadIdx.x; i < 2048; i += 256)
            ((float4*)cbs)[i] = ((const float4*)g_cbn[s])[i];
        for (int i = threadIdx.x; i < 512; i += 256)
            ((float*)Ms)[i] = ((const float*)g_M[s])[i];
        if (threadIdx.x < 8) bv[threadIdx.x] = g_bvec[s][threadIdx.x];
        __syncthreads();
        float ze[8];
#pragma unroll
        for (int d = 0; d < 8; d++) ze[d] = g_A[(s*8+d)*BT + col] + bv[d];
#pragma unroll
        for (int j = 0; j < 8; j++) {
            if (j >= s || !((c_dep[s] >> j) & 1)) continue;
#pragma unroll
            for (int dj = 0; dj < 8; dj++) {
                float cj = code[j][dj];
#pragma unroll
                for (int d = 0; d < 8; d++) ze[d] -= Ms[j][dj][d] * cj;
            }
        }
        float bvv = -1e30f; int bk = 0;
#pragma unroll 4
        for (int k = 0; k < 1024; k++) {
            float4 c0 = *(float4*)&cbs[k][0];
            float4 c1 = *(float4*)&cbs[k][4];
            float dt = ze[0]*c0.x + ze[1]*c0.y + ze[2]*c0.z + ze[3]*c0.w
                     + ze[4]*c1.x + ze[5]*c1.y + ze[6]*c1.z + ze[7]*c1.w;
            if (dt > bvv) { bvv = dt; bk = k; }
        }
        const float* cr = P.cb[c_mod[s]] + ((long long)c_sim[s]*1024 + bk)*8;
#pragma unroll
        for (int d = 0; d < 8; d++) {
            float cd = cr[d];
            code[s][d] = cd;
            float df = ze[d] - cd; cacc += df*df;
            g_code[(s*8+d)*BT + col] = cd;
        }
    }
    __shared__ float red[256];
    red[threadIdx.x] = cacc; __syncthreads();
    for (int st = 128; st; st >>= 1) {
        if (threadIdx.x < st) red[threadIdx.x] += red[threadIdx.x + st];
        __syncthreads();
    }
    if (threadIdx.x == 0) atomicAdd(&g_commit, (double)red[0]);
}

// ---- expand: grid (512 col-tiles, 16 ch-tiles) x 256 threads ----
__global__ void k_expand(float* __restrict__ out) {
    __shared__ __align__(16) float Wos[64][64];  // [k][ch_local]
    __shared__ __align__(16) float Cs[64][64];   // [k][col_local]
    __shared__ float obs[64][4];
    int col0 = blockIdx.x * 64, ch0 = blockIdx.y * 64;
    int b = col0 >> 12, t0 = col0 & 4095;
    int tid = threadIdx.x, tr = tid >> 4, tc = tid & 15;
    for (int i = tid; i < 1024; i += 256) {
        int k = i >> 4, q = i & 15;
        *(float4*)&Wos[k][q*4] = *(const float4*)&g_WoT[k*1024 + ch0 + q*4];
        *(float4*)&Cs[k][q*4]  = *(const float4*)&g_code[k*BT + col0 + q*4];
        if (i < 256) obs[i>>2][i&3] = g_obv[(ch0 + (i>>2))*4 + (i&3)];
    }
    __syncthreads();
    float mk = g_mask[b];
    long long obase = (long long)b*CT + (long long)ch0*4096 + t0 + tc*4;
    float acc[4][4] = {}, outs[4][4] = {};

#define MMA(K0,K1) \
    _Pragma("unroll") for (int k = (K0); k < (K1); k++) { \
        float4 w = *(float4*)&Wos[k][tr*4]; \
        float4 v = *(float4*)&Cs[k][tc*4]; \
        float wv[4] = {w.x,w.y,w.z,w.w}, cv[4] = {v.x,v.y,v.z,v.w}; \
        _Pragma("unroll") for (int i = 0; i < 4; i++) \
        _Pragma("unroll") for (int j = 0; j < 4; j++) acc[i][j] += wv[i]*cv[j]; }

#define FLUSH(TI,MM,SC) \
    _Pragma("unroll") for (int i = 0; i < 4; i++) { \
        float ob = obs[tr*4+i][MM]; float ov[4]; \
        _Pragma("unroll") for (int j = 0; j < 4; j++) { \
            float val = acc[i][j] + ob; ov[j] = val; \
            outs[i][j] += val * (SC); acc[i][j] = 0.f; } \
        float4 o = {ov[0],ov[1],ov[2],ov[3]}; \
        *(float4*)(out + (long long)(TI)*BCT + obase + (long long)(tr*4+i)*4096) = o; }

    MMA(0, 8)   FLUSH(1, 0, 1.f)
    MMA(8, 24)  FLUSH(2, 1, 1.f)
    MMA(24, 40) FLUSH(3, 2, 1.f)
    MMA(40, 64) FLUSH(4, 3, mk)
#pragma unroll
    for (int i = 0; i < 4; i++) {
        float4 o = {outs[i][0], outs[i][1], outs[i][2], outs[i][3]};
        *(float4*)(out + obase + (long long)(tr*4+i)*4096) = o;
    }
}

__global__ void k_final(float* out) {
    float v = (float)(g_commit / 262144.0);
    out[5*BCT] = v;
    out[5*BCT + 1] = v;
}

extern "C" void kernel_launch(void* const* d_in, const int* in_sizes, int n_in,
                              void* d_out, int out_size) {
    Ptrs P;
    for (int m = 0; m < 4; m++) {
        int base = 5 + m*5;
        P.iw[m] = (const float*)d_in[base];
        P.ib[m] = (const float*)d_in[base+1];
        P.cb[m] = (const float*)d_in[base+2];
        P.ow[m] = (const float*)d_in[base+3];
        P.ob[m] = (const float*)d_in[base+4];
    }
    const float* x = (const float*)d_in[0];
    float* out = (float*)d_out;

    k_init<<<1, 32>>>((const int*)d_in[2], (const int*)d_in[3], (const float*)d_in[4]);
    k_prepCB<<<8, 256>>>(P);
    k_prepW<<<64, 1024>>>(P);
    k_prepM<<<dim3(8,8), 512>>>(P);
    k_prepB<<<8, 256>>>(P);
    k_project<<<512, 256>>>(x);
    k_quant<<<128, 256>>>(P);
    k_expand<<<dim3(512,16), 256>>>(out);
    k_final<<<1, 1>>>(out);
}

// round 7
// speedup vs baseline: 1.1331x; 1.1331x over previous
#include <cuda_runtime.h>

typedef unsigned long long ull;

#define BT 32768
#define CT 4194304
static const long long BCT = 33554432LL;

struct Ptrs { const float *iw[4], *ib[4], *cb[4], *ow[4], *ob[4]; };

// stage order: p0, c0, c1, t0, t1, r0, r1, r2
__host__ __device__ constexpr int MODC(int s)      { return s==0?0 : s<3?1 : s<5?2 : 3; }
__host__ __device__ constexpr int SIMC(int s)      { return (s==0||s==1||s==3||s==5)?0 : (s==2||s==4||s==6)?1 : 2; }
__host__ __device__ constexpr unsigned DEPC(int s) { return s==0?0u : s==1?0u : s==2?2u : s==3?7u : s==4?15u : s==5?31u : s==6?63u : 127u; }

__constant__ int c_mod[8] = {0,1,1,2,2,3,3,3};
__constant__ int c_sim[8] = {0,0,1,0,1,0,1,2};
__constant__ unsigned c_dep[8] = {0,0,2,7,15,31,63,127};

__device__ __align__(16) ull   g_cbn2[8][512][8];  // normalized cb, k-pair packed
__device__ __align__(16) float g_Mn[8][8][8][8];   // NEGATED in_w_s @ out_w_j [s][j][dj][d]
__device__ float g_bvec[8][8];
__device__ __align__(16) float g_Wt[1024*64];      // [c][r]
__device__ __align__(16) float g_WoT[64*1024];     // [r][c]
__device__ float g_obv[1024*4];
__device__ float g_mask[8];
__device__ double g_commit;
__device__ __align__(16) float g_A[64*BT];
__device__ __align__(16) float g_code[64*BT];

__device__ __forceinline__ ull pk(float lo, float hi){ull r;asm("mov.b64 %0,{%1,%2};":"=l"(r):"f"(lo),"f"(hi));return r;}
__device__ __forceinline__ void upk(ull v,float&lo,float&hi){asm("mov.b64 {%0,%1},%2;":"=f"(lo),"=f"(hi):"l"(v));}
__device__ __forceinline__ ull fma2(ull a,ull b,ull c){ull d;asm("fma.rn.f32x2 %0,%1,%2,%3;":"=l"(d):"l"(a),"l"(b),"l"(c));return d;}
__device__ __forceinline__ ull mul2(ull a,ull b){ull d;asm("mul.rn.f32x2 %0,%1,%2;":"=l"(d):"l"(a),"l"(b));return d;}
__device__ __forceinline__ ull add2(ull a,ull b){ull d;asm("add.rn.f32x2 %0,%1,%2;":"=l"(d):"l"(a),"l"(b));return d;}

// ================= fused prep: grid 145 x 256 =================
__global__ void k_prep(Ptrs P, const int* noise, const int* recon, const float* rr) {
    int blk = blockIdx.x, tid = threadIdx.x;
    if (blk < 64) {                       // stack weights
        for (int e = 0; e < 4; e++) {
            int idx = blk*1024 + e*256 + tid;
            int c = idx>>6, r = idx&63, s = r>>3, d = r&7;
            int m = c_mod[s], si = c_sim[s];
            g_Wt[c*64+r]    = P.iw[m][(si*8+d)*1024 + c];
            g_WoT[r*1024+c] = P.ow[m][((long long)si*1024 + c)*8 + d];
        }
        if (blk == 0) {
            for (int e = 0; e < 4; e++) {
                int cc = e*256 + tid;
                g_obv[cc*4+0] = P.ob[0][cc];
                g_obv[cc*4+1] = P.ob[1][cc] + P.ob[1][1024+cc];
                g_obv[cc*4+2] = P.ob[2][cc] + P.ob[2][1024+cc];
                g_obv[cc*4+3] = P.ob[3][cc] + P.ob[3][1024+cc] + P.ob[3][2048+cc];
            }
        }
    } else if (blk < 72) {                // normalize + pair-pack codebooks
        int s = blk-64, m = c_mod[s], si = c_sim[s];
        const float* src = P.cb[m] + (long long)si*8192;
        for (int h = 0; h < 2; h++) {
            int kp = h*256 + tid;
            float v0[8], v1[8], s0 = 0.f, s1 = 0.f;
#pragma unroll
            for (int d = 0; d < 8; d++) {
                v0[d] = src[(2*kp)*8+d];   s0 += v0[d]*v0[d];
                v1[d] = src[(2*kp+1)*8+d]; s1 += v1[d]*v1[d];
            }
            float n0 = fmaxf(__fsqrt_rn(s0), 1e-12f);
            float n1 = fmaxf(__fsqrt_rn(s1), 1e-12f);
#pragma unroll
            for (int d = 0; d < 8; d++)
                g_cbn2[s][kp][d] = pk(__fdiv_rn(v0[d],n0), __fdiv_rn(v1[d],n1));
        }
    } else if (blk < 136) {               // M[s][j] = -in_w_s @ out_w_j  (warp per dj)
        int m2 = blk - 72, s = m2>>3, j = m2&7;
        if (((c_dep[s]>>j)&1) == 0) return;
        int w = tid>>5, lane = tid&31;
        const float* iwp = P.iw[c_mod[s]] + (long long)(c_sim[s]*8)*1024;
        const float* owp = P.ow[c_mod[j]] + (long long)c_sim[j]*8192;
        int dj = w;
        for (int d = 0; d < 8; d++) {
            float a = 0.f;
            for (int i = 0; i < 32; i++) {
                int c = lane + 32*i;
                a += iwp[d*1024 + c] * owp[c*8 + dj];
            }
#pragma unroll
            for (int o = 16; o; o >>= 1) a += __shfl_down_sync(~0u, a, o);
            if (lane == 0) g_Mn[s][j][dj][d] = -a;
        }
    } else if (blk < 144) {               // bvec
        int s = blk-136, d = tid>>5, lane = tid&31;
        const float* iwp = P.iw[c_mod[s]] + (c_sim[s]*8 + d)*1024;
        float a = 0.f;
        for (int j = 0; j < 8; j++) if ((c_dep[s]>>j)&1) {
            const float* ob = P.ob[c_mod[j]] + c_sim[j]*1024;
            for (int c = lane; c < 1024; c += 32) a += iwp[c] * ob[c];
        }
#pragma unroll
        for (int o = 16; o; o >>= 1) a += __shfl_down_sync(~0u, a, o);
        if (lane == 0) g_bvec[s][d] = P.ib[c_mod[s]][c_sim[s]*8 + d] - a;
    } else {                              // mask + commit reset
        if (tid == 0) g_commit = 0.0;
        if (tid < 8) g_mask[tid] = noise[tid] ? (recon[tid] ? 1.f : 0.f) : rr[tid];
    }
}

// ================= project: A = Wt^T @ x, f32x2. grid 256 x 256 =================
__global__ void __launch_bounds__(256) k_project(const float* __restrict__ x) {
    __shared__ __align__(16) float Ws[64][64];
    __shared__ __align__(16) float Xs[64][128];
    int col0 = blockIdx.x * 128;
    int b = col0 >> 12, t0 = col0 & 4095;
    const float* xb = x + (long long)b*CT + t0;
    int tid = threadIdx.x, tr = tid>>4, tc = tid&15;
    ull acc[4][4];
#pragma unroll
    for (int i = 0; i < 4; i++)
#pragma unroll
        for (int p = 0; p < 4; p++) acc[i][p] = 0ULL;

    for (int c0 = 0; c0 < 1024; c0 += 64) {
        __syncthreads();
#pragma unroll
        for (int e = 0; e < 4; e++) {
            int i = e*256 + tid, k = i>>4, q = i&15;
            *(float4*)&Ws[k][q*4] = *(const float4*)&g_Wt[(c0+k)*64 + q*4];
        }
#pragma unroll
        for (int e = 0; e < 8; e++) {
            int i = e*256 + tid, k = i>>5, q = i&31;
            *(float4*)&Xs[k][q*4] = *(const float4*)&xb[(long long)(c0+k)*4096 + q*4];
        }
        __syncthreads();
#pragma unroll 4
        for (int k = 0; k < 64; k++) {
            float4 w = *(float4*)&Ws[k][tr*4];
            ull wd0 = pk(w.x,w.x), wd1 = pk(w.y,w.y), wd2 = pk(w.z,w.z), wd3 = pk(w.w,w.w);
            ulonglong2 xa = *(ulonglong2*)&Xs[k][tc*8];
            ulonglong2 xv = *(ulonglong2*)&Xs[k][tc*8+4];
            ull xp[4] = {xa.x, xa.y, xv.x, xv.y};
            ull wd[4] = {wd0, wd1, wd2, wd3};
#pragma unroll
            for (int i = 0; i < 4; i++)
#pragma unroll
                for (int p = 0; p < 4; p++) acc[i][p] = fma2(wd[i], xp[p], acc[i][p]);
        }
    }
#pragma unroll
    for (int i = 0; i < 4; i++) {
        long long base = (long long)(tr*4+i)*BT + col0 + tc*8;
        ulonglong2 o0 = {acc[i][0], acc[i][1]}, o1 = {acc[i][2], acc[i][3]};
        *(ulonglong2*)&g_A[base]     = o0;
        *(ulonglong2*)&g_A[base + 4] = o1;
    }
}

// ================= quantize: grid 256 x 128 (1 col/thread) =================
__global__ void __launch_bounds__(128) k_quant(Ptrs P) {
    __shared__ __align__(16) ull cbs[512][8];
    __shared__ float Ms[8][8][8];
    __shared__ float bvs[8];
    __shared__ float red[4];
    int tid = threadIdx.x;
    int col = blockIdx.x * 128 + tid;
    float code[8][8];
    float cacc = 0.f;
#pragma unroll
    for (int s = 0; s < 8; s++) {
        __syncthreads();
        {
            const ulonglong2* src = (const ulonglong2*)&g_cbn2[s][0][0];
            ulonglong2* dst = (ulonglong2*)&cbs[0][0];
#pragma unroll
            for (int e = 0; e < 16; e++) dst[e*128 + tid] = src[e*128 + tid];
        }
#pragma unroll
        for (int e = 0; e < 4; e++) (&Ms[0][0][0])[e*128+tid] = (&g_Mn[s][0][0][0])[e*128+tid];
        if (tid < 8) bvs[tid] = g_bvec[s][tid];
        __syncthreads();

        float ze[8];
#pragma unroll
        for (int d = 0; d < 8; d++) ze[d] = g_A[(s*8+d)*(long long)BT + col] + bvs[d];
#pragma unroll
        for (int j = 0; j < 8; j++) {
            if (j >= s || !((DEPC(s)>>j)&1)) continue;
#pragma unroll
            for (int dj = 0; dj < 8; dj++) {
                float cj = code[j][dj];
#pragma unroll
                for (int d = 0; d < 8; d++) ze[d] += Ms[j][dj][d]*cj;  // Ms is negated
            }
        }
        ull zd[8];
#pragma unroll
        for (int d = 0; d < 8; d++) zd[d] = pk(ze[d], ze[d]);

        float b0=-1e30f, b1=-1e30f, b2=-1e30f, b3=-1e30f;
        int i0=0, i1=0, i2=0, i3=0;
#pragma unroll 2
        for (int kp = 0; kp < 512; kp += 2) {
            {
                ulonglong2 ca=*(ulonglong2*)&cbs[kp][0], cb2=*(ulonglong2*)&cbs[kp][2];
                ulonglong2 cc=*(ulonglong2*)&cbs[kp][4], cd=*(ulonglong2*)&cbs[kp][6];
                ull a0 = mul2(zd[0],ca.x); a0=fma2(zd[1],ca.y,a0);
                a0=fma2(zd[2],cb2.x,a0);   a0=fma2(zd[3],cb2.y,a0);
                ull a1 = mul2(zd[4],cc.x); a1=fma2(zd[5],cc.y,a1);
                a1=fma2(zd[6],cd.x,a1);    a1=fma2(zd[7],cd.y,a1);
                float lo,hi; upk(add2(a0,a1),lo,hi);
                if (lo > b0) { b0=lo; i0=2*kp; }
                if (hi > b1) { b1=hi; i1=2*kp+1; }
            }
            {
                int kq = kp+1;
                ulonglong2 ca=*(ulonglong2*)&cbs[kq][0], cb2=*(ulonglong2*)&cbs[kq][2];
                ulonglong2 cc=*(ulonglong2*)&cbs[kq][4], cd=*(ulonglong2*)&cbs[kq][6];
                ull a0 = mul2(zd[0],ca.x); a0=fma2(zd[1],ca.y,a0);
                a0=fma2(zd[2],cb2.x,a0);   a0=fma2(zd[3],cb2.y,a0);
                ull a1 = mul2(zd[4],cc.x); a1=fma2(zd[5],cc.y,a1);
                a1=fma2(zd[6],cd.x,a1);    a1=fma2(zd[7],cd.y,a1);
                float lo,hi; upk(add2(a0,a1),lo,hi);
                if (lo > b2) { b2=lo; i2=2*kq; }
                if (hi > b3) { b3=hi; i3=2*kq+1; }
            }
        }
        float bb = b0; int bk = i0;
        if (b1>bb || (b1==bb && i1<bk)) { bb=b1; bk=i1; }
        if (b2>bb || (b2==bb && i2<bk)) { bb=b2; bk=i2; }
        if (b3>bb || (b3==bb && i3<bk)) { bb=b3; bk=i3; }

        const float* cr = P.cb[MODC(s)] + ((long long)SIMC(s)*1024 + bk)*8;
        float4 r0 = *(const float4*)cr, r1 = *(const float4*)(cr+4);
        float cd8[8] = {r0.x,r0.y,r0.z,r0.w,r1.x,r1.y,r1.z,r1.w};
#pragma unroll
        for (int d = 0; d < 8; d++) {
            code[s][d] = cd8[d];
            float df = ze[d]-cd8[d]; cacc += df*df;
            g_code[(s*8+d)*(long long)BT + col] = cd8[d];
        }
    }
#pragma unroll
    for (int o = 16; o; o >>= 1) cacc += __shfl_down_sync(~0u, cacc, o);
    if ((tid&31)==0) red[tid>>5] = cacc;
    __syncthreads();
    if (tid == 0) atomicAdd(&g_commit, (double)(red[0]+red[1]+red[2]+red[3]));
}

// ================= expand: grid (256,16) x 256, f32x2 =================
__global__ void __launch_bounds__(256) k_expand(float* __restrict__ out) {
    __shared__ __align__(16) float Wos[64][64];
    __shared__ __align__(16) float Cs[64][128];
    int col0 = blockIdx.x * 128, ch0 = blockIdx.y * 64;
    int b = col0>>12, t0 = col0&4095;
    int tid = threadIdx.x, tr = tid>>5, tc = tid&31;
#pragma unroll
    for (int e = 0; e < 4; e++) {
        int i = e*256 + tid, k = i>>4, q = i&15;
        *(float4*)&Wos[k][q*4] = *(const float4*)&g_WoT[k*1024 + ch0 + q*4];
    }
#pragma unroll
    for (int e = 0; e < 8; e++) {
        int i = e*256 + tid, k = i>>5, q = i&31;
        *(float4*)&Cs[k][q*4] = *(const float4*)&g_code[(long long)k*BT + col0 + q*4];
    }
    __syncthreads();
    float mk = g_mask[b];
    ull mkd = pk(mk, mk);
    long long obase = (long long)b*CT + (long long)ch0*4096 + t0 + tc*4;
    ull acc[8][2], outs[8][2];
#pragma unroll
    for (int i = 0; i < 8; i++) { acc[i][0]=acc[i][1]=0ULL; outs[i][0]=outs[i][1]=0ULL; }

#define MMAK(K0,K1) \
    _Pragma("unroll 4") for (int k = (K0); k < (K1); k++) { \
        float4 w0 = *(float4*)&Wos[k][tr*8]; \
        float4 w1 = *(float4*)&Wos[k][tr*8+4]; \
        ulonglong2 xa = *(ulonglong2*)&Cs[k][tc*4]; \
        ull wd[8] = {pk(w0.x,w0.x),pk(w0.y,w0.y),pk(w0.z,w0.z),pk(w0.w,w0.w), \
                     pk(w1.x,w1.x),pk(w1.y,w1.y),pk(w1.z,w1.z),pk(w1.w,w1.w)}; \
        _Pragma("unroll") for (int i = 0; i < 8; i++) { \
            acc[i][0] = fma2(wd[i], xa.x, acc[i][0]); \
            acc[i][1] = fma2(wd[i], xa.y, acc[i][1]); } }

#define FLUSHP(TI, MM, MASKED) \
    _Pragma("unroll") for (int i = 0; i < 8; i++) { \
        float ob = g_obv[(ch0 + tr*8 + i)*4 + (MM)]; \
        ull obd = pk(ob, ob); \
        ull v0 = add2(acc[i][0], obd), v1 = add2(acc[i][1], obd); \
        long long rowo = (long long)(TI)*BCT + obase + (long long)(tr*8+i)*4096; \
        ulonglong2 st = {v0, v1}; \
        *(ulonglong2*)(out + rowo) = st; \
        if (MASKED) { outs[i][0] = fma2(mkd, v0, outs[i][0]); outs[i][1] = fma2(mkd, v1, outs[i][1]); } \
        else        { outs[i][0] = add2(outs[i][0], v0);      outs[i][1] = add2(outs[i][1], v1); } \
        acc[i][0] = 0ULL; acc[i][1] = 0ULL; }

    MMAK(0, 8)   FLUSHP(1, 0, 0)
    MMAK(8, 24)  FLUSHP(2, 1, 0)
    MMAK(24, 40) FLUSHP(3, 2, 0)
    MMAK(40, 64) FLUSHP(4, 3, 1)
#pragma unroll
    for (int i = 0; i < 8; i++) {
        long long rowo = obase + (long long)(tr*8+i)*4096;
        ulonglong2 st = {outs[i][0], outs[i][1]};
        *(ulonglong2*)(out + rowo) = st;
    }
    if (blockIdx.x == 0 && blockIdx.y == 0 && tid == 0) {
        float v = (float)(g_commit / 262144.0);
        out[5*BCT] = v;
        out[5*BCT + 1] = v;
    }
}

extern "C" void kernel_launch(void* const* d_in, const int* in_sizes, int n_in,
                              void* d_out, int out_size) {
    Ptrs P;
    for (int m = 0; m < 4; m++) {
        int base = 5 + m*5;
        P.iw[m] = (const float*)d_in[base];
        P.ib[m] = (const float*)d_in[base+1];
        P.cb[m] = (const float*)d_in[base+2];
        P.ow[m] = (const float*)d_in[base+3];
        P.ob[m] = (const float*)d_in[base+4];
    }
    const float* x = (const float*)d_in[0];
    float* out = (float*)d_out;

    k_prep<<<145, 256>>>(P, (const int*)d_in[2], (const int*)d_in[3], (const float*)d_in[4]);
    k_project<<<256, 256>>>(x);
    k_quant<<<256, 128>>>(P);
    k_expand<<<dim3(256,16), 256>>>(out);
}

// round 8
// speedup vs baseline: 1.1691x; 1.0318x over previous
#include <cuda_runtime.h>

typedef unsigned long long ull;

#define BT 32768
#define CT 4194304
static const long long BCT = 33554432LL;

struct Ptrs { const float *iw[4], *ib[4], *cb[4], *ow[4], *ob[4]; };

__constant__ int c_mod[8] = {0,1,1,2,2,3,3,3};
__constant__ int c_sim[8] = {0,0,1,0,1,0,1,2};
__constant__ unsigned c_dep[8] = {0,0,2,7,15,31,63,127};

__device__ __align__(16) ulonglong2 g_cbq[8][8][256];  // [s][d][chunk], chunk=4 codes k-pair packed
__device__ __align__(16) float g_cbraw[8][1024][8];    // raw codebook per stage
__device__ __align__(16) float g_Mn[8][8][8][8];       // NEGATED in_w_s @ out_w_j [s][j][dj][d]
__device__ float g_bvec[8][8];
__device__ __align__(16) float g_Wt[1024*64];          // [c][r]
__device__ __align__(16) float g_WoT[64*1024];         // [r][c]
__device__ float g_obv[1024*4];
__device__ float g_mask[8];
__device__ double g_commit;
__device__ __align__(16) float g_A[64*BT];
__device__ __align__(16) float g_code[64*BT];

__device__ __forceinline__ ull pk(float lo, float hi){ull r;asm("mov.b64 %0,{%1,%2};":"=l"(r):"f"(lo),"f"(hi));return r;}
__device__ __forceinline__ void upk(ull v,float&lo,float&hi){asm("mov.b64 {%0,%1},%2;":"=f"(lo),"=f"(hi):"l"(v));}
__device__ __forceinline__ ull fma2(ull a,ull b,ull c){ull d;asm("fma.rn.f32x2 %0,%1,%2,%3;":"=l"(d):"l"(a),"l"(b),"l"(c));return d;}
__device__ __forceinline__ ull mul2(ull a,ull b){ull d;asm("mul.rn.f32x2 %0,%1,%2;":"=l"(d):"l"(a),"l"(b));return d;}
__device__ __forceinline__ ull add2(ull a,ull b){ull d;asm("add.rn.f32x2 %0,%1,%2;":"=l"(d):"l"(a),"l"(b));return d;}
__device__ __forceinline__ void stcs2(void* p, ull a, ull b){
    asm volatile("st.global.cs.v2.b64 [%0], {%1,%2};" :: "l"(p), "l"(a), "l"(b) : "memory");
}

// ================= fused prep: grid 145 x 256 =================
__global__ void k_prep(Ptrs P, const int* noise, const int* recon, const float* rr) {
    int blk = blockIdx.x, tid = threadIdx.x;
    if (blk < 64) {                       // stack weights
        for (int e = 0; e < 4; e++) {
            int idx = blk*1024 + e*256 + tid;
            int c = idx>>6, r = idx&63, s = r>>3, d = r&7;
            int m = c_mod[s], si = c_sim[s];
            g_Wt[c*64+r]    = P.iw[m][(si*8+d)*1024 + c];
            g_WoT[r*1024+c] = P.ow[m][((long long)si*1024 + c)*8 + d];
        }
        if (blk == 0) {
            for (int e = 0; e < 4; e++) {
                int cc = e*256 + tid;
                g_obv[cc*4+0] = P.ob[0][cc];
                g_obv[cc*4+1] = P.ob[1][cc] + P.ob[1][1024+cc];
                g_obv[cc*4+2] = P.ob[2][cc] + P.ob[2][1024+cc];
                g_obv[cc*4+3] = P.ob[3][cc] + P.ob[3][1024+cc] + P.ob[3][2048+cc];
            }
        }
    } else if (blk < 72) {                // raw copy + normalize + SoA-pack codebooks
        int s = blk-64, m = c_mod[s], si = c_sim[s];
        const float* src = P.cb[m] + (long long)si*8192;
#pragma unroll
        for (int e = 0; e < 8; e++) {     // raw copy (2048 float4)
            int i = e*256 + tid;
            ((float4*)&g_cbraw[s][0][0])[i] = ((const float4*)src)[i];
        }
        for (int h = 0; h < 2; h++) {
            int kp = h*256 + tid;         // pair index (codes 2kp, 2kp+1)
            float v0[8], v1[8], s0 = 0.f, s1 = 0.f;
#pragma unroll
            for (int d = 0; d < 8; d++) {
                v0[d] = src[(2*kp)*8+d];   s0 += v0[d]*v0[d];
                v1[d] = src[(2*kp+1)*8+d]; s1 += v1[d]*v1[d];
            }
            float n0 = fmaxf(__fsqrt_rn(s0), 1e-12f);
            float n1 = fmaxf(__fsqrt_rn(s1), 1e-12f);
#pragma unroll
            for (int d = 0; d < 8; d++)
                ((ull*)&g_cbq[s][d][0])[kp] = pk(__fdiv_rn(v0[d],n0), __fdiv_rn(v1[d],n1));
        }
    } else if (blk < 136) {               // M[s][j] = -in_w_s @ out_w_j  (warp per dj)
        int m2 = blk - 72, s = m2>>3, j = m2&7;
        if (((c_dep[s]>>j)&1) == 0) return;
        int w = tid>>5, lane = tid&31;
        const float* iwp = P.iw[c_mod[s]] + (long long)(c_sim[s]*8)*1024;
        const float* owp = P.ow[c_mod[j]] + (long long)c_sim[j]*8192;
        int dj = w;
        for (int d = 0; d < 8; d++) {
            float a = 0.f;
            for (int i = 0; i < 32; i++) {
                int c = lane + 32*i;
                a += iwp[d*1024 + c] * owp[c*8 + dj];
            }
#pragma unroll
            for (int o = 16; o; o >>= 1) a += __shfl_down_sync(~0u, a, o);
            if (lane == 0) g_Mn[s][j][dj][d] = -a;
        }
    } else if (blk < 144) {               // bvec
        int s = blk-136, d = tid>>5, lane = tid&31;
        const float* iwp = P.iw[c_mod[s]] + (c_sim[s]*8 + d)*1024;
        float a = 0.f;
        for (int j = 0; j < 8; j++) if ((c_dep[s]>>j)&1) {
            const float* ob = P.ob[c_mod[j]] + c_sim[j]*1024;
            for (int c = lane; c < 1024; c += 32) a += iwp[c] * ob[c];
        }
#pragma unroll
        for (int o = 16; o; o >>= 1) a += __shfl_down_sync(~0u, a, o);
        if (lane == 0) g_bvec[s][d] = P.ib[c_mod[s]][c_sim[s]*8 + d] - a;
    } else {                              // mask + commit reset
        if (tid == 0) g_commit = 0.0;
        if (tid < 8) g_mask[tid] = noise[tid] ? (recon[tid] ? 1.f : 0.f) : rr[tid];
    }
}

// ================= project: A = Wt^T @ x, f32x2. grid 256 x 256 =================
__global__ void __launch_bounds__(256) k_project(const float* __restrict__ x) {
    __shared__ __align__(16) float Ws[64][64];
    __shared__ __align__(16) float Xs[64][128];
    int col0 = blockIdx.x * 128;
    int b = col0 >> 12, t0 = col0 & 4095;
    const float* xb = x + (long long)b*CT + t0;
    int tid = threadIdx.x, tr = tid>>4, tc = tid&15;
    ull acc[4][4];
#pragma unroll
    for (int i = 0; i < 4; i++)
#pragma unroll
        for (int p = 0; p < 4; p++) acc[i][p] = 0ULL;

    for (int c0 = 0; c0 < 1024; c0 += 64) {
        __syncthreads();
#pragma unroll
        for (int e = 0; e < 4; e++) {
            int i = e*256 + tid, k = i>>4, q = i&15;
            *(float4*)&Ws[k][q*4] = *(const float4*)&g_Wt[(c0+k)*64 + q*4];
        }
#pragma unroll
        for (int e = 0; e < 8; e++) {
            int i = e*256 + tid, k = i>>5, q = i&31;
            *(float4*)&Xs[k][q*4] = *(const float4*)&xb[(long long)(c0+k)*4096 + q*4];
        }
        __syncthreads();
#pragma unroll 4
        for (int k = 0; k < 64; k++) {
            float4 w = *(float4*)&Ws[k][tr*4];
            ull wd0 = pk(w.x,w.x), wd1 = pk(w.y,w.y), wd2 = pk(w.z,w.z), wd3 = pk(w.w,w.w);
            ulonglong2 xa = *(ulonglong2*)&Xs[k][tc*8];
            ulonglong2 xv = *(ulonglong2*)&Xs[k][tc*8+4];
            ull xp[4] = {xa.x, xa.y, xv.x, xv.y};
            ull wd[4] = {wd0, wd1, wd2, wd3};
#pragma unroll
            for (int i = 0; i < 4; i++)
#pragma unroll
                for (int p = 0; p < 4; p++) acc[i][p] = fma2(wd[i], xp[p], acc[i][p]);
        }
    }
#pragma unroll
    for (int i = 0; i < 4; i++) {
        long long base = (long long)(tr*4+i)*BT + col0 + tc*8;
        ulonglong2 o0 = {acc[i][0], acc[i][1]}, o1 = {acc[i][2], acc[i][3]};
        *(ulonglong2*)&g_A[base]     = o0;
        *(ulonglong2*)&g_A[base + 4] = o1;
    }
}

// ================= quantize: grid 512 x 256; 8 lanes/col, 2 cols/thread =================
// dyn smem: cbs[8][256] ulonglong2 (32KB) | Ms 512f (2KB) | codeS [64][76]f (19KB) | bvs 8f | red 8f
__global__ void __launch_bounds__(256, 4) k_quant() {
    extern __shared__ char sm[];
    ulonglong2* cbs  = (ulonglong2*)sm;
    float* Ms   = (float*)(sm + 32768);
    float* codeS= (float*)(sm + 32768 + 2048);
    float* bvs  = codeS + 64*76;
    float* red  = bvs + 8;

    int tid = threadIdx.x;
    int lane = tid & 31;
    int sub = tid & 7;          // d-lane / k-split lane
    int cg  = tid >> 3;         // 0..31 column-pair group
    int cl0 = cg*2, cl1 = cl0 + 1;
    int col0 = blockIdx.x*64 + cl0;
    float cacc = 0.f;

#pragma unroll 1
    for (int s = 0; s < 8; s++) {
        __syncthreads();
        {
            const ulonglong2* src = &g_cbq[s][0][0];
#pragma unroll
            for (int e = 0; e < 8; e++) cbs[e*256 + tid] = src[e*256 + tid];
        }
        Ms[tid]       = (&g_Mn[s][0][0][0])[tid];
        Ms[256 + tid] = (&g_Mn[s][0][0][0])[256 + tid];
        if (tid < 8) bvs[tid] = g_bvec[s][tid];
        __syncthreads();

        // ze for d = sub, two columns
        float2 zin = *(const float2*)&g_A[(s*8+sub)*(long long)BT + col0];
        float ze0 = zin.x + bvs[sub];
        float ze1 = zin.y + bvs[sub];
        unsigned dep = c_dep[s];
        for (int j = 0; j < 8; j++) {
            if (!((dep>>j)&1)) continue;
#pragma unroll
            for (int dj = 0; dj < 8; dj++) {
                float m = Ms[(j*8+dj)*8 + sub];   // negated
                ze0 = fmaf(m, codeS[cl0*76 + j*9 + dj], ze0);
                ze1 = fmaf(m, codeS[cl1*76 + j*9 + dj], ze1);
            }
        }
        // gather full ze vectors (packed) from the 8 lanes of this column group
        ull zd0[8], zd1[8];
#pragma unroll
        for (int d = 0; d < 8; d++) {
            float a = __shfl_sync(~0u, ze0, (lane & 24) | d);
            float b = __shfl_sync(~0u, ze1, (lane & 24) | d);
            zd0[d] = pk(a,a); zd1[d] = pk(b,b);
        }
        // each lane scans 128 codes: chunks i*8+sub, 4 codes each
        float bb0 = -1e30f, bb1 = -1e30f;
        int bk0 = 0, bk1 = 0;
#pragma unroll 4
        for (int i = 0; i < 32; i++) {
            int ch = i*8 + sub;
            ulonglong2 cv = cbs[ch];
            ull a0 = mul2(zd0[0], cv.x), b0 = mul2(zd0[0], cv.y);
            ull a1 = mul2(zd1[0], cv.x), b1 = mul2(zd1[0], cv.y);
#pragma unroll
            for (int d = 1; d < 8; d++) {
                cv = cbs[d*256 + ch];
                a0 = fma2(zd0[d], cv.x, a0); b0 = fma2(zd0[d], cv.y, b0);
                a1 = fma2(zd1[d], cv.x, a1); b1 = fma2(zd1[d], cv.y, b1);
            }
            int k0 = ch*4;
            float v0,v1,v2,v3;
            upk(a0,v0,v1); upk(b0,v2,v3);
            if (v0 > bb0) { bb0=v0; bk0=k0;   }
            if (v1 > bb0) { bb0=v1; bk0=k0+1; }
            if (v2 > bb0) { bb0=v2; bk0=k0+2; }
            if (v3 > bb0) { bb0=v3; bk0=k0+3; }
            upk(a1,v0,v1); upk(b1,v2,v3);
            if (v0 > bb1) { bb1=v0; bk1=k0;   }
            if (v1 > bb1) { bb1=v1; bk1=k0+1; }
            if (v2 > bb1) { bb1=v2; bk1=k0+2; }
            if (v3 > bb1) { bb1=v3; bk1=k0+3; }
        }
        // reduce over the 8 lanes (first-index tie-break)
#pragma unroll
        for (int off = 4; off; off >>= 1) {
            float o0 = __shfl_down_sync(~0u, bb0, off, 8);
            int   q0 = __shfl_down_sync(~0u, bk0, off, 8);
            float o1 = __shfl_down_sync(~0u, bb1, off, 8);
            int   q1 = __shfl_down_sync(~0u, bk1, off, 8);
            if (o0 > bb0 || (o0 == bb0 && q0 < bk0)) { bb0=o0; bk0=q0; }
            if (o1 > bb1 || (o1 == bb1 && q1 < bk1)) { bb1=o1; bk1=q1; }
        }
        bk0 = __shfl_sync(~0u, bk0, lane & 24);
        bk1 = __shfl_sync(~0u, bk1, lane & 24);

        float cd0 = g_cbraw[s][bk0][sub];
        float cd1 = g_cbraw[s][bk1][sub];
        codeS[cl0*76 + s*9 + sub] = cd0;
        codeS[cl1*76 + s*9 + sub] = cd1;
        float2 st2; st2.x = cd0; st2.y = cd1;
        *(float2*)&g_code[(s*8+sub)*(long long)BT + col0] = st2;
        float d0 = ze0 - cd0, d1 = ze1 - cd1;
        cacc += d0*d0 + d1*d1;
    }
#pragma unroll
    for (int o = 16; o; o >>= 1) cacc += __shfl_down_sync(~0u, cacc, o);
    if (lane == 0) red[tid>>5] = cacc;
    __syncthreads();
    if (tid == 0) {
        float t = 0.f;
#pragma unroll
        for (int w = 0; w < 8; w++) t += red[w];
        atomicAdd(&g_commit, (double)t);
    }
}

// ================= expand: grid (256,16) x 256, f32x2 + streaming stores =================
__global__ void __launch_bounds__(256) k_expand(float* __restrict__ out) {
    __shared__ __align__(16) float Wos[64][64];
    __shared__ __align__(16) float Cs[64][128];
    int col0 = blockIdx.x * 128, ch0 = blockIdx.y * 64;
    int b = col0>>12, t0 = col0&4095;
    int tid = threadIdx.x, tr = tid>>5, tc = tid&31;
#pragma unroll
    for (int e = 0; e < 4; e++) {
        int i = e*256 + tid, k = i>>4, q = i&15;
        *(float4*)&Wos[k][q*4] = *(const float4*)&g_WoT[k*1024 + ch0 + q*4];
    }
#pragma unroll
    for (int e = 0; e < 8; e++) {
        int i = e*256 + tid, k = i>>5, q = i&31;
        *(float4*)&Cs[k][q*4] = *(const float4*)&g_code[(long long)k*BT + col0 + q*4];
    }
    __syncthreads();
    float mk = g_mask[b];
    ull mkd = pk(mk, mk);
    long long obase = (long long)b*CT + (long long)ch0*4096 + t0 + tc*4;
    ull acc[8][2], outs[8][2];
#pragma unroll
    for (int i = 0; i < 8; i++) { acc[i][0]=acc[i][1]=0ULL; outs[i][0]=outs[i][1]=0ULL; }

#define MMAK(K0,K1) \
    _Pragma("unroll 4") for (int k = (K0); k < (K1); k++) { \
        float4 w0 = *(float4*)&Wos[k][tr*8]; \
        float4 w1 = *(float4*)&Wos[k][tr*8+4]; \
        ulonglong2 xa = *(ulonglong2*)&Cs[k][tc*4]; \
        ull wd[8] = {pk(w0.x,w0.x),pk(w0.y,w0.y),pk(w0.z,w0.z),pk(w0.w,w0.w), \
                     pk(w1.x,w1.x),pk(w1.y,w1.y),pk(w1.z,w1.z),pk(w1.w,w1.w)}; \
        _Pragma("unroll") for (int i = 0; i < 8; i++) { \
            acc[i][0] = fma2(wd[i], xa.x, acc[i][0]); \
            acc[i][1] = fma2(wd[i], xa.y, acc[i][1]); } }

#define FLUSHP(TI, MM, MASKED) \
    _Pragma("unroll") for (int i = 0; i < 8; i++) { \
        float ob = g_obv[(ch0 + tr*8 + i)*4 + (MM)]; \
        ull obd = pk(ob, ob); \
        ull v0 = add2(acc[i][0], obd), v1 = add2(acc[i][1], obd); \
        long long rowo = (long long)(TI)*BCT + obase + (long long)(tr*8+i)*4096; \
        stcs2(out + rowo, v0, v1); \
        if (MASKED) { outs[i][0] = fma2(mkd, v0, outs[i][0]); outs[i][1] = fma2(mkd, v1, outs[i][1]); } \
        else        { outs[i][0] = add2(outs[i][0], v0);      outs[i][1] = add2(outs[i][1], v1); } \
        acc[i][0] = 0ULL; acc[i][1] = 0ULL; }

    MMAK(0, 8)   FLUSHP(1, 0, 0)
    MMAK(8, 24)  FLUSHP(2, 1, 0)
    MMAK(24, 40) FLUSHP(3, 2, 0)
    MMAK(40, 64) FLUSHP(4, 3, 1)
#pragma unroll
    for (int i = 0; i < 8; i++) {
        long long rowo = obase + (long long)(tr*8+i)*4096;
        stcs2(out + rowo, outs[i][0], outs[i][1]);
    }
    if (blockIdx.x == 0 && blockIdx.y == 0 && tid == 0) {
        float v = (float)(g_commit / 262144.0);
        out[5*BCT] = v;
        out[5*BCT + 1] = v;
    }
}

extern "C" void kernel_launch(void* const* d_in, const int* in_sizes, int n_in,
                              void* d_out, int out_size) {
    Ptrs P;
    for (int m = 0; m < 4; m++) {
        int base = 5 + m*5;
        P.iw[m] = (const float*)d_in[base];
        P.ib[m] = (const float*)d_in[base+1];
        P.cb[m] = (const float*)d_in[base+2];
        P.ow[m] = (const float*)d_in[base+3];
        P.ob[m] = (const float*)d_in[base+4];
    }
    const float* x = (const float*)d_in[0];
    float* out = (float*)d_out;

    const int QSMEM = 32768 + 2048 + 64*76*4 + 64;
    static bool attr_set = false;
    if (!attr_set) {
        cudaFuncSetAttribute(k_quant, cudaFuncAttributeMaxDynamicSharedMemorySize, QSMEM);
        attr_set = true;
    }

    k_prep<<<145, 256>>>(P, (const int*)d_in[2], (const int*)d_in[3], (const float*)d_in[4]);
    k_project<<<256, 256>>>(x);
    k_quant<<<512, 256, QSMEM>>>();
    k_expand<<<dim3(256,16), 256>>>(out);
}